// round 5
// baseline (speedup 1.0000x reference)
#include <cuda_runtime.h>
#include <math.h>
#include <float.h>

#define NN 50000
#define FF 128
#define HH 256
#define CC 512

// ---------------- scratch (device globals; no allocation) ----------------
__device__ float    g_inv[NN];
__device__ int      g_cnt[NN];
__device__ float    g_prop[NN * HH];   // propagated features (<=256 wide)
__device__ float    g_h[NN * HH];      // hidden activations h1 / h2
__device__ float    g_h3[NN * CC];     // logits (512 wide)
__device__ float    g_z[NN];
__device__ float    g_zp[NN];
__device__ float    g_score[NN];
__device__ int      g_cluster[NN];
__device__ unsigned g_segmax[CC];
__device__ int      g_segidx[CC];
__device__ int      g_intra[CC];

// ---------------- helpers ----------------
static inline int cdiv(int a, int b) { return (a + b - 1) / b; }

__device__ __forceinline__ unsigned enc_f(float f) {
    unsigned u = __float_as_uint(f);
    return (u & 0x80000000u) ? ~u : (u | 0x80000000u);
}
__device__ __forceinline__ float dec_f(unsigned u) {
    return (u & 0x80000000u) ? __uint_as_float(u & 0x7fffffffu) : __uint_as_float(~u);
}

__device__ __forceinline__ void red4(float* p, float a, float b, float c, float d) {
    asm volatile("red.global.add.v4.f32 [%0], {%1,%2,%3,%4};"
                 :: "l"(p), "f"(a), "f"(b), "f"(c), "f"(d) : "memory");
}

// ---------------- small kernels ----------------
__global__ void k_zero_i32(int* p, int n) {
    int i = blockIdx.x * blockDim.x + threadIdx.x;
    if (i < n) p[i] = 0;
}
__global__ void k_zero_f32(float* p, int n) {
    int i = blockIdx.x * blockDim.x + threadIdx.x;
    if (i < n) p[i] = 0.0f;
}
__global__ void k_reset_cluster(unsigned* mx, int* idx, int* cnt, int c) {
    int i = blockIdx.x * blockDim.x + threadIdx.x;
    if (i < c) { mx[i] = 0u; idx[i] = 0x7fffffff; cnt[i] = 0; }
}
__global__ void k_count(const int* __restrict__ dst, int e, int* __restrict__ cnt) {
    int i = blockIdx.x * blockDim.x + threadIdx.x;
    if (i < e) atomicAdd(&cnt[dst[i]], 1);
}
__global__ void k_inv(const int* __restrict__ cnt, float* __restrict__ inv, int n) {
    int i = blockIdx.x * blockDim.x + threadIdx.x;
    if (i < n) inv[i] = 1.0f / sqrtf((float)cnt[i] + 1.0f);
}

// out[row] = feat[row] * inv[row]^2  (self-loop term), vectorized float4
template <int D>
__global__ void k_self(const float* __restrict__ feat, const float* __restrict__ inv,
                       float* __restrict__ out, int n) {
    int gid = blockIdx.x * blockDim.x + threadIdx.x;
    int tot = n * (D / 4);
    if (gid >= tot) return;
    int row = gid / (D / 4);
    float iv = inv[row];
    float s = iv * iv;
    float4 v = ((const float4*)feat)[gid];
    v.x *= s; v.y *= s; v.z *= s; v.w *= s;
    ((float4*)out)[gid] = v;
}

// one warp per edge; vector atomics into out[dst]
template <int D>
__global__ void k_edge(const int* __restrict__ src, const int* __restrict__ dst,
                       const float* __restrict__ inv, const float* __restrict__ feat,
                       float* __restrict__ out, int e) {
    int w = (blockIdx.x * blockDim.x + threadIdx.x) >> 5;
    if (w >= e) return;
    int lane = threadIdx.x & 31;
    int s = src[w];
    int d = dst[w];
    float coef = inv[s] * inv[d];
    const float4* fs = (const float4*)(feat + (size_t)s * D);
    float* fo = out + (size_t)d * D;
#pragma unroll
    for (int c = lane; c < D / 4; c += 32) {
        float4 v = __ldg(&fs[c]);
        red4(fo + c * 4, v.x * coef, v.y * coef, v.z * coef, v.w * coef);
    }
}

// ---------------- SGEMM: C = relu?(A[M,K] @ B[K,N] + bias) ----------------
// 128x128 tile, BK=8, 256 threads, 8x8 per thread
__global__ __launch_bounds__(256) void sgemm(const float* __restrict__ A,
                                             const float* __restrict__ B,
                                             const float* __restrict__ bias,
                                             float* __restrict__ C,
                                             int M, int N, int K, int relu) {
    __shared__ float As[8][128];
    __shared__ float Bs[8][128];
    int tid = threadIdx.x;
    int bx = blockIdx.x, by = blockIdx.y;
    int tcol = tid & 15;
    int trow = tid >> 4;

    float acc[8][8];
#pragma unroll
    for (int i = 0; i < 8; i++)
#pragma unroll
        for (int j = 0; j < 8; j++) acc[i][j] = 0.0f;

    int aRow = tid >> 1;
    int aCol = (tid & 1) * 4;
    int bRow = tid >> 5;
    int bCol = (tid & 31) * 4;
    int grA = by * 128 + aRow;
    const float* Aptr = A + (size_t)grA * K + aCol;
    const float* Bptr = B + (size_t)bRow * N + bx * 128 + bCol;

    for (int k0 = 0; k0 < K; k0 += 8) {
        float4 av = make_float4(0.f, 0.f, 0.f, 0.f);
        if (grA < M) av = *(const float4*)(Aptr + k0);
        As[aCol + 0][aRow] = av.x;
        As[aCol + 1][aRow] = av.y;
        As[aCol + 2][aRow] = av.z;
        As[aCol + 3][aRow] = av.w;
        float4 bv = *(const float4*)(Bptr + (size_t)k0 * N);
        *(float4*)&Bs[bRow][bCol] = bv;
        __syncthreads();
#pragma unroll
        for (int k = 0; k < 8; k++) {
            float4 a0 = *(float4*)&As[k][trow * 8];
            float4 a1 = *(float4*)&As[k][trow * 8 + 4];
            float4 b0 = *(float4*)&Bs[k][tcol * 8];
            float4 b1 = *(float4*)&Bs[k][tcol * 8 + 4];
            float ar[8] = {a0.x, a0.y, a0.z, a0.w, a1.x, a1.y, a1.z, a1.w};
            float br[8] = {b0.x, b0.y, b0.z, b0.w, b1.x, b1.y, b1.z, b1.w};
#pragma unroll
            for (int i = 0; i < 8; i++)
#pragma unroll
                for (int j = 0; j < 8; j++) acc[i][j] = fmaf(ar[i], br[j], acc[i][j]);
        }
        __syncthreads();
    }

    int col0 = bx * 128 + tcol * 8;
    float4 bi0 = *(const float4*)&bias[col0];
    float4 bi1 = *(const float4*)&bias[col0 + 4];
    float bb[8] = {bi0.x, bi0.y, bi0.z, bi0.w, bi1.x, bi1.y, bi1.z, bi1.w};
#pragma unroll
    for (int i = 0; i < 8; i++) {
        int row = by * 128 + trow * 8 + i;
        if (row < M) {
            float o[8];
#pragma unroll
            for (int j = 0; j < 8; j++) {
                float v = acc[i][j] + bb[j];
                if (relu) v = fmaxf(v, 0.0f);
                o[j] = v;
            }
            *(float4*)&C[(size_t)row * N + col0] = make_float4(o[0], o[1], o[2], o[3]);
            *(float4*)&C[(size_t)row * N + col0 + 4] = make_float4(o[4], o[5], o[6], o[7]);
        }
    }
}

// ---------------- softmax + argmax (warp per row, 512 cols) ----------------
__global__ void k_softmax_argmax(const float* __restrict__ h3, float* __restrict__ S,
                                 int* __restrict__ cluster, int n) {
    int w = (blockIdx.x * blockDim.x + threadIdx.x) >> 5;
    if (w >= n) return;
    int lane = threadIdx.x & 31;
    const float* hr = h3 + (size_t)w * CC;
    float v[16];
    float mx = -FLT_MAX;
#pragma unroll
    for (int k = 0; k < 16; k++) {
        v[k] = hr[lane + 32 * k];
        mx = fmaxf(mx, v[k]);
    }
#pragma unroll
    for (int o = 16; o; o >>= 1) mx = fmaxf(mx, __shfl_xor_sync(0xffffffffu, mx, o));
    float sum = 0.0f;
#pragma unroll
    for (int k = 0; k < 16; k++) {
        v[k] = expf(v[k] - mx);
        sum += v[k];
    }
#pragma unroll
    for (int o = 16; o; o >>= 1) sum += __shfl_xor_sync(0xffffffffu, sum, o);
    float* Sr = S + (size_t)w * CC;
    float best = -1.0f;
    int bidx = 0x7fffffff;
#pragma unroll
    for (int k = 0; k < 16; k++) {
        float s = v[k] / sum;
        Sr[lane + 32 * k] = s;
        int idx = lane + 32 * k;
        if (s > best || (s == best && idx < bidx)) { best = s; bidx = idx; }
    }
#pragma unroll
    for (int o = 16; o; o >>= 1) {
        float ob = __shfl_xor_sync(0xffffffffu, best, o);
        int oi = __shfl_xor_sync(0xffffffffu, bidx, o);
        if (ob > best || (ob == best && oi < bidx)) { best = ob; bidx = oi; }
    }
    if (lane == 0) cluster[w] = bidx;
}

// ---------------- score-layer kernels ----------------
__global__ void k_intra_count(const int* __restrict__ src, const int* __restrict__ dst,
                              const int* __restrict__ cl, int e,
                              int* __restrict__ cntdeg, int* __restrict__ cntcl) {
    int i = blockIdx.x * blockDim.x + threadIdx.x;
    if (i >= e) return;
    int s = src[i], d = dst[i];
    int ci = cl[s];
    if (ci == cl[d]) {
        atomicAdd(&cntdeg[d], 1);
        atomicAdd(&cntcl[ci], 1);
    }
}
__global__ void k_z(const float* __restrict__ x, const float* __restrict__ Ws,
                    float* __restrict__ z, int n) {
    int w = (blockIdx.x * blockDim.x + threadIdx.x) >> 5;
    if (w >= n) return;
    int lane = threadIdx.x & 31;
    float acc = 0.0f;
#pragma unroll
    for (int c = lane; c < FF; c += 32) acc += x[(size_t)w * FF + c] * Ws[c];
#pragma unroll
    for (int o = 16; o; o >>= 1) acc += __shfl_xor_sync(0xffffffffu, acc, o);
    if (lane == 0) z[w] = acc;
}
__global__ void k_self1(const float* __restrict__ z, const float* __restrict__ inv,
                        float* __restrict__ zp, int n) {
    int i = blockIdx.x * blockDim.x + threadIdx.x;
    if (i < n) { float iv = inv[i]; zp[i] = z[i] * iv * iv; }
}
__global__ void k_edge_score(const int* __restrict__ src, const int* __restrict__ dst,
                             const int* __restrict__ cl, const float* __restrict__ inv,
                             const float* __restrict__ z, float* __restrict__ zp, int e) {
    int i = blockIdx.x * blockDim.x + threadIdx.x;
    if (i >= e) return;
    int s = src[i], d = dst[i];
    if (cl[s] == cl[d]) atomicAdd(&zp[d], z[s] * inv[s] * inv[d]);
}
__global__ void k_score(const float* __restrict__ zp, const float* __restrict__ bs,
                        float* __restrict__ score, int n) {
    int i = blockIdx.x * blockDim.x + threadIdx.x;
    if (i < n) score[i] = tanhf(zp[i] + bs[0]);
}
__global__ void k_segmax(const float* __restrict__ score, const int* __restrict__ cl,
                         unsigned* __restrict__ mx, int n) {
    int i = blockIdx.x * blockDim.x + threadIdx.x;
    if (i < n) atomicMax(&mx[cl[i]], enc_f(score[i]));
}
__global__ void k_segidx(const float* __restrict__ score, const int* __restrict__ cl,
                         const unsigned* __restrict__ mx, int* __restrict__ idx, int n) {
    int i = blockIdx.x * blockDim.x + threadIdx.x;
    if (i >= n) return;
    int c = cl[i];
    if (score[i] >= dec_f(mx[c])) atomicMin(&idx[c], i);
}
__global__ void k_adj(const int* __restrict__ src, const int* __restrict__ dst,
                      const int* __restrict__ cl, const int* __restrict__ intra,
                      float* __restrict__ adj, int e) {
    int i = blockIdx.x * blockDim.x + threadIdx.x;
    if (i >= e) return;
    int ci = cl[src[i]], cj = cl[dst[i]];
    if (ci != cj && intra[ci] > 0 && intra[cj] > 0) adj[ci * CC + cj] = 1.0f;
}
__global__ void k_finalize(const float* __restrict__ x, const int* __restrict__ batch,
                           const unsigned* __restrict__ mx, const int* __restrict__ idx,
                           const int* __restrict__ intra,
                           float* __restrict__ outx, float* __restrict__ outb, int n) {
    int c = blockIdx.x;
    bool ne = intra[c] > 0;
    float alpha = ne ? dec_f(mx[c]) : 0.0f;
    int safe = min(idx[c], n - 1);
    for (int f = threadIdx.x; f < FF; f += blockDim.x)
        outx[c * FF + f] = x[(size_t)safe * FF + f] * alpha;
    if (threadIdx.x == 0) outb[c] = ne ? (float)batch[safe] : 0.0f;
}

// ---------------- launcher ----------------
extern "C" void kernel_launch(void* const* d_in, const int* in_sizes, int n_in,
                              void* d_out, int out_size) {
    const float* x = (const float*)d_in[0];
    const int* ei = (const int*)d_in[1];
    const int* batch = (const int*)d_in[2];
    const float* W1 = (const float*)d_in[3];
    const float* b1 = (const float*)d_in[4];
    const float* W2 = (const float*)d_in[5];
    const float* b2 = (const float*)d_in[6];
    const float* W3 = (const float*)d_in[7];
    const float* b3 = (const float*)d_in[8];
    const float* Ws = (const float*)d_in[9];
    const float* bs = (const float*)d_in[10];

    int n = in_sizes[2];       // batch has N elements
    int E = in_sizes[1] / 2;
    const int* src = ei;
    const int* dst = ei + E;

    float* out = (float*)d_out;
    const int off_adj = CC * FF;           // 65536
    const int off_batch = off_adj + CC * CC;  // 327680
    const int off_s = off_batch + CC;      // 328192

    // scratch addresses
    float *inv, *prop, *h, *h3, *z, *zp, *score;
    int *cnt, *cluster, *segidx, *intra;
    unsigned* segmax;
    cudaGetSymbolAddress((void**)&inv, g_inv);
    cudaGetSymbolAddress((void**)&cnt, g_cnt);
    cudaGetSymbolAddress((void**)&prop, g_prop);
    cudaGetSymbolAddress((void**)&h, g_h);
    cudaGetSymbolAddress((void**)&h3, g_h3);
    cudaGetSymbolAddress((void**)&z, g_z);
    cudaGetSymbolAddress((void**)&zp, g_zp);
    cudaGetSymbolAddress((void**)&score, g_score);
    cudaGetSymbolAddress((void**)&cluster, g_cluster);
    cudaGetSymbolAddress((void**)&segmax, g_segmax);
    cudaGetSymbolAddress((void**)&segidx, g_segidx);
    cudaGetSymbolAddress((void**)&intra, g_intra);

    const int T = 256;
    int ewarp_blocks = cdiv(E, 8);   // warp per edge

    // ----- degree + inv -----
    k_zero_i32<<<cdiv(n, T), T>>>(cnt, n);
    k_count<<<cdiv(E, T), T>>>(dst, E, cnt);
    k_inv<<<cdiv(n, T), T>>>(cnt, inv, n);

    // ----- layer 1: P = A_hat x ; h1 = relu(P@W1 + b1) -----
    k_self<FF><<<cdiv(n * (FF / 4), T), T>>>(x, inv, prop, n);
    k_edge<FF><<<ewarp_blocks, T>>>(src, dst, inv, x, prop, E);
    {
        dim3 g(HH / 128, cdiv(n, 128));
        sgemm<<<g, 256>>>(prop, W1, b1, h, n, HH, FF, 1);
    }
    // ----- layer 2 -----
    k_self<HH><<<cdiv(n * (HH / 4), T), T>>>(h, inv, prop, n);
    k_edge<HH><<<ewarp_blocks, T>>>(src, dst, inv, h, prop, E);
    {
        dim3 g(HH / 128, cdiv(n, 128));
        sgemm<<<g, 256>>>(prop, W2, b2, h, n, HH, HH, 1);
    }
    // ----- layer 3 -----
    k_self<HH><<<cdiv(n * (HH / 4), T), T>>>(h, inv, prop, n);
    k_edge<HH><<<ewarp_blocks, T>>>(src, dst, inv, h, prop, E);
    {
        dim3 g(CC / 128, cdiv(n, 128));
        sgemm<<<g, 256>>>(prop, W3, b3, h3, n, CC, HH, 1);
    }

    // ----- softmax + cluster assignment (writes S) -----
    k_softmax_argmax<<<cdiv(n * 32, T), T>>>(h3, out + off_s, cluster, n);

    // ----- score layer on intra-cluster subgraph -----
    k_zero_i32<<<cdiv(n, T), T>>>(cnt, n);
    k_reset_cluster<<<cdiv(CC, T), T>>>(segmax, segidx, intra, CC);
    k_intra_count<<<cdiv(E, T), T>>>(src, dst, cluster, E, cnt, intra);
    k_inv<<<cdiv(n, T), T>>>(cnt, inv, n);
    k_z<<<cdiv(n * 32, T), T>>>(x, Ws, z, n);
    k_self1<<<cdiv(n, T), T>>>(z, inv, zp, n);
    k_edge_score<<<cdiv(E, T), T>>>(src, dst, cluster, inv, z, zp, E);
    k_score<<<cdiv(n, T), T>>>(zp, bs, score, n);

    // ----- per-cluster top-1 selection -----
    k_segmax<<<cdiv(n, T), T>>>(score, cluster, segmax, n);
    k_segidx<<<cdiv(n, T), T>>>(score, cluster, segmax, segidx, n);

    // ----- outputs: new_adj, new_x, new_batch -----
    k_zero_f32<<<cdiv(CC * CC, T), T>>>(out + off_adj, CC * CC);
    k_adj<<<cdiv(E, T), T>>>(src, dst, cluster, intra, out + off_adj, E);
    k_finalize<<<CC, 128>>>(x, batch, segmax, segidx, intra, out, out + off_batch, n);
}

// round 6
// speedup vs baseline: 1.3488x; 1.3488x over previous
#include <cuda_runtime.h>
#include <math.h>
#include <float.h>

#define NN 50000
#define FF 128
#define HH 256
#define CC 512
#define MAXE 800000
typedef unsigned long long U64;

// ---------------- scratch (device globals; no allocation) ----------------
__device__ float    g_inv[NN];
__device__ int      g_cnt[NN];
__device__ int      g_eoff[NN + 1];
__device__ int      g_esrc[MAXE];
__device__ float    g_prop[NN * HH];
__device__ float    g_h[NN * HH];
__device__ float    g_h3[NN * CC];
__device__ float    g_z[NN];
__device__ float    g_score[NN];
__device__ int      g_cluster[NN];
__device__ unsigned g_segmax[CC];
__device__ int      g_segidx[CC];
__device__ int      g_intra[CC];

static inline int cdiv(int a, int b) { return (a + b - 1) / b; }

__device__ __forceinline__ unsigned enc_f(float f) {
    unsigned u = __float_as_uint(f);
    return (u & 0x80000000u) ? ~u : (u | 0x80000000u);
}
__device__ __forceinline__ float dec_f(unsigned u) {
    return (u & 0x80000000u) ? __uint_as_float(u & 0x7fffffffu) : __uint_as_float(~u);
}

#define FMA2(d, a, b) asm("fma.rn.f32x2 %0, %1, %2, %0;" : "+l"(d) : "l"(a), "l"(b))

// ---------------- tiny kernels ----------------
__global__ void k_zero_i32(int* p, int n) {
    int i = blockIdx.x * blockDim.x + threadIdx.x;
    if (i < n) p[i] = 0;
}
__global__ void k_zero_f32(float* p, int n) {
    int i = blockIdx.x * blockDim.x + threadIdx.x;
    if (i < n) p[i] = 0.0f;
}
__global__ void k_reset_cluster(unsigned* mx, int* idx, int* cnt, int c) {
    int i = blockIdx.x * blockDim.x + threadIdx.x;
    if (i < c) { mx[i] = 0u; idx[i] = 0x7fffffff; cnt[i] = 0; }
}
__global__ void k_count(const int* __restrict__ dst, int e, int* __restrict__ cnt) {
    int i = blockIdx.x * blockDim.x + threadIdx.x;
    if (i < e) atomicAdd(&cnt[dst[i]], 1);
}
__global__ void k_inv(const int* __restrict__ cnt, float* __restrict__ inv, int n) {
    int i = blockIdx.x * blockDim.x + threadIdx.x;
    if (i < n) inv[i] = rsqrtf((float)cnt[i] + 1.0f);
}

// single-block exclusive scan over n counts -> eoff[0..n]
#define SCAN_T 1024
__global__ void k_scan(const int* __restrict__ cnt, int* __restrict__ eoff, int n) {
    __shared__ int sums[SCAN_T];
    int t = threadIdx.x;
    int ch = (n + SCAN_T - 1) / SCAN_T;
    int lo = t * ch, hi = min(lo + ch, n);
    int s = 0;
    for (int i = lo; i < hi; i++) s += cnt[i];
    sums[t] = s;
    __syncthreads();
    for (int off = 1; off < SCAN_T; off <<= 1) {
        int v = (t >= off) ? sums[t - off] : 0;
        __syncthreads();
        sums[t] += v;
        __syncthreads();
    }
    int run = sums[t] - s;  // exclusive prefix
    for (int i = lo; i < hi; i++) { eoff[i] = run; run += cnt[i]; }
    if (t == SCAN_T - 1) eoff[n] = run;
}

__global__ void k_scatter(const int* __restrict__ src, const int* __restrict__ dst,
                          const int* __restrict__ eoff, int* __restrict__ cur,
                          int* __restrict__ esrc, int e) {
    int i = blockIdx.x * blockDim.x + threadIdx.x;
    if (i >= e) return;
    int d = dst[i];
    int p = eoff[d] + atomicAdd(&cur[d], 1);
    esrc[p] = src[i];
}

// ---------------- per-node propagation: out[v] = inv[v]^2 x[v] + sum inv[s]inv[v] x[s]
template <int D>
__global__ void k_aggr(const int* __restrict__ eoff, const int* __restrict__ esrc,
                       const float* __restrict__ inv, const float* __restrict__ feat,
                       float* __restrict__ out, int n) {
    int w = (blockIdx.x * blockDim.x + threadIdx.x) >> 5;
    if (w >= n) return;
    int lane = threadIdx.x & 31;
    constexpr int V = D / 128;  // float4 per lane
    float ivd = inv[w];
    float s2 = ivd * ivd;
    float4 acc[V];
    const float4* fv = (const float4*)(feat + (size_t)w * D);
#pragma unroll
    for (int q = 0; q < V; q++) {
        float4 v = __ldg(&fv[lane + 32 * q]);
        acc[q] = make_float4(v.x * s2, v.y * s2, v.z * s2, v.w * s2);
    }
    int e = eoff[w], e1 = eoff[w + 1];
    for (; e + 2 <= e1; e += 2) {
        int s0 = __ldg(&esrc[e]);
        int s1 = __ldg(&esrc[e + 1]);
        float c0 = __ldg(&inv[s0]) * ivd;
        float c1 = __ldg(&inv[s1]) * ivd;
        const float4* f0 = (const float4*)(feat + (size_t)s0 * D);
        const float4* f1 = (const float4*)(feat + (size_t)s1 * D);
#pragma unroll
        for (int q = 0; q < V; q++) {
            float4 v0 = __ldg(&f0[lane + 32 * q]);
            float4 v1 = __ldg(&f1[lane + 32 * q]);
            acc[q].x = fmaf(v0.x, c0, acc[q].x); acc[q].y = fmaf(v0.y, c0, acc[q].y);
            acc[q].z = fmaf(v0.z, c0, acc[q].z); acc[q].w = fmaf(v0.w, c0, acc[q].w);
            acc[q].x = fmaf(v1.x, c1, acc[q].x); acc[q].y = fmaf(v1.y, c1, acc[q].y);
            acc[q].z = fmaf(v1.z, c1, acc[q].z); acc[q].w = fmaf(v1.w, c1, acc[q].w);
        }
    }
    if (e < e1) {
        int s0 = __ldg(&esrc[e]);
        float c0 = __ldg(&inv[s0]) * ivd;
        const float4* f0 = (const float4*)(feat + (size_t)s0 * D);
#pragma unroll
        for (int q = 0; q < V; q++) {
            float4 v0 = __ldg(&f0[lane + 32 * q]);
            acc[q].x = fmaf(v0.x, c0, acc[q].x); acc[q].y = fmaf(v0.y, c0, acc[q].y);
            acc[q].z = fmaf(v0.z, c0, acc[q].z); acc[q].w = fmaf(v0.w, c0, acc[q].w);
        }
    }
    float4* ov = (float4*)(out + (size_t)w * D);
#pragma unroll
    for (int q = 0; q < V; q++) ov[lane + 32 * q] = acc[q];
}

// ---------------- SGEMM (FFMA2): C = relu?(A[M,K]@B[K,N] + bias) ----------------
// 128x128 tile, BK=8, 256 threads, 8x8/thread, double-buffered smem,
// A tile stored splatted so the inner loop is LDS.128 + fma.rn.f32x2 only.
__global__ __launch_bounds__(256) void sgemm2(const float* __restrict__ A,
                                              const float* __restrict__ B,
                                              const float* __restrict__ bias,
                                              float* __restrict__ C,
                                              int M, int N, int K, int relu) {
    __shared__ float As[2][8][256];  // [buf][k][2*m + {0,1}] (splatted pairs)
    __shared__ float Bs[2][8][128];
    int tid = threadIdx.x;
    int bx = blockIdx.x, by = blockIdx.y;
    int trow = tid >> 4, tcol = tid & 15;

    // A stage: 128 rows x 8 k = 1024 floats; thread loads float4 along K
    int aRow = tid >> 1;
    int aCol = (tid & 1) * 4;
    int grA = by * 128 + aRow;
    bool aval = grA < M;
    const float* Aptr = A + (size_t)grA * K + aCol;
    // B stage: 8 rows x 128 cols
    int bRow = tid >> 5, bCol = (tid & 31) * 4;
    const float* Bptr = B + (size_t)bRow * N + bx * 128 + bCol;

    U64 acc[8][4];
#pragma unroll
    for (int i = 0; i < 8; i++)
#pragma unroll
        for (int j = 0; j < 4; j++) acc[i][j] = 0ull;

    float4 av = make_float4(0.f, 0.f, 0.f, 0.f), bv;
    if (aval) av = *(const float4*)(Aptr);
    bv = *(const float4*)(Bptr);
    {
        float a4[4] = {av.x, av.y, av.z, av.w};
#pragma unroll
        for (int q = 0; q < 4; q++) {
            As[0][aCol + q][2 * aRow] = a4[q];
            As[0][aCol + q][2 * aRow + 1] = a4[q];
        }
        *(float4*)&Bs[0][bRow][bCol] = bv;
    }
    __syncthreads();

    int nt = K >> 3;
    for (int t = 0; t < nt; t++) {
        int cur = t & 1;
        if (t + 1 < nt) {
            av = make_float4(0.f, 0.f, 0.f, 0.f);
            if (aval) av = *(const float4*)(Aptr + (t + 1) * 8);
            bv = *(const float4*)(Bptr + (size_t)(t + 1) * 8 * N);
        }
#pragma unroll
        for (int k = 0; k < 8; k++) {
            const ulonglong2* ap = (const ulonglong2*)&As[cur][k][trow * 16];
            const ulonglong2* bp = (const ulonglong2*)&Bs[cur][k][tcol * 8];
            ulonglong2 a01 = ap[0], a23 = ap[1], a45 = ap[2], a67 = ap[3];
            ulonglong2 b01 = bp[0], b23 = bp[1];
            U64 a[8] = {a01.x, a01.y, a23.x, a23.y, a45.x, a45.y, a67.x, a67.y};
            U64 b[4] = {b01.x, b01.y, b23.x, b23.y};
#pragma unroll
            for (int i = 0; i < 8; i++)
#pragma unroll
                for (int j = 0; j < 4; j++) FMA2(acc[i][j], a[i], b[j]);
        }
        __syncthreads();
        if (t + 1 < nt) {
            int nb = (t + 1) & 1;
            float a4[4] = {av.x, av.y, av.z, av.w};
#pragma unroll
            for (int q = 0; q < 4; q++) {
                As[nb][aCol + q][2 * aRow] = a4[q];
                As[nb][aCol + q][2 * aRow + 1] = a4[q];
            }
            *(float4*)&Bs[nb][bRow][bCol] = bv;
        }
        __syncthreads();
    }

    int col0 = bx * 128 + tcol * 8;
    float bb[8];
#pragma unroll
    for (int j = 0; j < 8; j++) bb[j] = bias[col0 + j];
    union { U64 u; float2 f; } cv;
#pragma unroll
    for (int i = 0; i < 8; i++) {
        int row = by * 128 + trow * 8 + i;
        if (row < M) {
            float o[8];
#pragma unroll
            for (int j = 0; j < 4; j++) {
                cv.u = acc[i][j];
                float v0 = cv.f.x + bb[2 * j], v1 = cv.f.y + bb[2 * j + 1];
                if (relu) { v0 = fmaxf(v0, 0.0f); v1 = fmaxf(v1, 0.0f); }
                o[2 * j] = v0; o[2 * j + 1] = v1;
            }
            *(float4*)&C[(size_t)row * N + col0] = make_float4(o[0], o[1], o[2], o[3]);
            *(float4*)&C[(size_t)row * N + col0 + 4] = make_float4(o[4], o[5], o[6], o[7]);
        }
    }
}

// ---------------- softmax + argmax (warp per row, 512 cols) ----------------
__global__ void k_softmax_argmax(const float* __restrict__ h3, float* __restrict__ S,
                                 int* __restrict__ cluster, int n) {
    int w = (blockIdx.x * blockDim.x + threadIdx.x) >> 5;
    if (w >= n) return;
    int lane = threadIdx.x & 31;
    const float* hr = h3 + (size_t)w * CC;
    float v[16];
    float mx = -FLT_MAX;
#pragma unroll
    for (int k = 0; k < 16; k++) {
        v[k] = hr[lane + 32 * k];
        mx = fmaxf(mx, v[k]);
    }
#pragma unroll
    for (int o = 16; o; o >>= 1) mx = fmaxf(mx, __shfl_xor_sync(0xffffffffu, mx, o));
    float sum = 0.0f;
#pragma unroll
    for (int k = 0; k < 16; k++) {
        v[k] = expf(v[k] - mx);
        sum += v[k];
    }
#pragma unroll
    for (int o = 16; o; o >>= 1) sum += __shfl_xor_sync(0xffffffffu, sum, o);
    float* Sr = S + (size_t)w * CC;
    float best = -1.0f;
    int bidx = 0x7fffffff;
#pragma unroll
    for (int k = 0; k < 16; k++) {
        float s = v[k] / sum;
        Sr[lane + 32 * k] = s;
        int idx = lane + 32 * k;
        if (s > best || (s == best && idx < bidx)) { best = s; bidx = idx; }
    }
#pragma unroll
    for (int o = 16; o; o >>= 1) {
        float ob = __shfl_xor_sync(0xffffffffu, best, o);
        int oi = __shfl_xor_sync(0xffffffffu, bidx, o);
        if (ob > best || (ob == best && oi < bidx)) { best = ob; bidx = oi; }
    }
    if (lane == 0) cluster[w] = bidx;
}

// ---------------- score layer on intra-cluster subgraph (CSR-based) ----------------
__global__ void k_intra(const int* __restrict__ eoff, const int* __restrict__ esrc,
                        const int* __restrict__ cl, int n,
                        int* __restrict__ cntdeg, int* __restrict__ cntcl) {
    int v = blockIdx.x * blockDim.x + threadIdx.x;
    if (v >= n) return;
    int c = cl[v];
    int cnt = 0;
    int e1 = eoff[v + 1];
    for (int e = eoff[v]; e < e1; e++) cnt += (cl[esrc[e]] == c);
    cntdeg[v] = cnt;
    if (cnt) atomicAdd(&cntcl[c], cnt);
}
__global__ void k_z(const float* __restrict__ x, const float* __restrict__ Ws,
                    float* __restrict__ z, int n) {
    int w = (blockIdx.x * blockDim.x + threadIdx.x) >> 5;
    if (w >= n) return;
    int lane = threadIdx.x & 31;
    float acc = 0.0f;
#pragma unroll
    for (int c = lane; c < FF; c += 32) acc += x[(size_t)w * FF + c] * Ws[c];
#pragma unroll
    for (int o = 16; o; o >>= 1) acc += __shfl_xor_sync(0xffffffffu, acc, o);
    if (lane == 0) z[w] = acc;
}
__global__ void k_scoreagg(const int* __restrict__ eoff, const int* __restrict__ esrc,
                           const int* __restrict__ cl, const float* __restrict__ inv,
                           const float* __restrict__ z, const float* __restrict__ bs,
                           float* __restrict__ score, int n) {
    int v = blockIdx.x * blockDim.x + threadIdx.x;
    if (v >= n) return;
    int c = cl[v];
    float iv = inv[v];
    float acc = z[v] * iv * iv;
    int e1 = eoff[v + 1];
    for (int e = eoff[v]; e < e1; e++) {
        int s = esrc[e];
        if (cl[s] == c) acc = fmaf(z[s] * inv[s], iv, acc);
    }
    score[v] = tanhf(acc + bs[0]);
}
__global__ void k_segmax(const float* __restrict__ score, const int* __restrict__ cl,
                         unsigned* __restrict__ mx, int n) {
    int i = blockIdx.x * blockDim.x + threadIdx.x;
    if (i < n) atomicMax(&mx[cl[i]], enc_f(score[i]));
}
__global__ void k_segidx(const float* __restrict__ score, const int* __restrict__ cl,
                         const unsigned* __restrict__ mx, int* __restrict__ idx, int n) {
    int i = blockIdx.x * blockDim.x + threadIdx.x;
    if (i >= n) return;
    int c = cl[i];
    if (score[i] >= dec_f(mx[c])) atomicMin(&idx[c], i);
}
__global__ void k_adj(const int* __restrict__ src, const int* __restrict__ dst,
                      const int* __restrict__ cl, const int* __restrict__ intra,
                      float* __restrict__ adj, int e) {
    int i = blockIdx.x * blockDim.x + threadIdx.x;
    if (i >= e) return;
    int ci = cl[src[i]], cj = cl[dst[i]];
    if (ci != cj && intra[ci] > 0 && intra[cj] > 0) adj[ci * CC + cj] = 1.0f;
}
__global__ void k_finalize(const float* __restrict__ x, const int* __restrict__ batch,
                           const unsigned* __restrict__ mx, const int* __restrict__ idx,
                           const int* __restrict__ intra,
                           float* __restrict__ outx, float* __restrict__ outb, int n) {
    int c = blockIdx.x;
    bool ne = intra[c] > 0;
    float alpha = ne ? dec_f(mx[c]) : 0.0f;
    int safe = min(idx[c], n - 1);
    for (int f = threadIdx.x; f < FF; f += blockDim.x)
        outx[c * FF + f] = x[(size_t)safe * FF + f] * alpha;
    if (threadIdx.x == 0) outb[c] = ne ? (float)batch[safe] : 0.0f;
}

// ---------------- launcher ----------------
extern "C" void kernel_launch(void* const* d_in, const int* in_sizes, int n_in,
                              void* d_out, int out_size) {
    const float* x = (const float*)d_in[0];
    const int* ei = (const int*)d_in[1];
    const int* batch = (const int*)d_in[2];
    const float* W1 = (const float*)d_in[3];
    const float* b1 = (const float*)d_in[4];
    const float* W2 = (const float*)d_in[5];
    const float* b2 = (const float*)d_in[6];
    const float* W3 = (const float*)d_in[7];
    const float* b3 = (const float*)d_in[8];
    const float* Ws = (const float*)d_in[9];
    const float* bs = (const float*)d_in[10];

    int n = in_sizes[2];
    int E = in_sizes[1] / 2;
    const int* src = ei;
    const int* dst = ei + E;

    float* out = (float*)d_out;
    const int off_adj = CC * FF;
    const int off_batch = off_adj + CC * CC;
    const int off_s = off_batch + CC;

    float *inv, *prop, *h, *h3, *z, *score;
    int *cnt, *eoff, *esrc, *cluster, *segidx, *intra;
    unsigned* segmax;
    cudaGetSymbolAddress((void**)&inv, g_inv);
    cudaGetSymbolAddress((void**)&cnt, g_cnt);
    cudaGetSymbolAddress((void**)&eoff, g_eoff);
    cudaGetSymbolAddress((void**)&esrc, g_esrc);
    cudaGetSymbolAddress((void**)&prop, g_prop);
    cudaGetSymbolAddress((void**)&h, g_h);
    cudaGetSymbolAddress((void**)&h3, g_h3);
    cudaGetSymbolAddress((void**)&z, g_z);
    cudaGetSymbolAddress((void**)&score, g_score);
    cudaGetSymbolAddress((void**)&cluster, g_cluster);
    cudaGetSymbolAddress((void**)&segmax, g_segmax);
    cudaGetSymbolAddress((void**)&segidx, g_segidx);
    cudaGetSymbolAddress((void**)&intra, g_intra);

    const int T = 256;
    int aggr_blocks = cdiv(n, 8);  // warp per node, 8 warps/block

    // ----- degree, inv, CSR build -----
    k_zero_i32<<<cdiv(n, T), T>>>(cnt, n);
    k_count<<<cdiv(E, T), T>>>(dst, E, cnt);
    k_inv<<<cdiv(n, T), T>>>(cnt, inv, n);
    k_scan<<<1, SCAN_T>>>(cnt, eoff, n);
    k_zero_i32<<<cdiv(n, T), T>>>(cnt, n);  // reuse as scatter cursor
    k_scatter<<<cdiv(E, T), T>>>(src, dst, eoff, cnt, esrc, E);

    // ----- layer 1 -----
    k_aggr<FF><<<aggr_blocks, T>>>(eoff, esrc, inv, x, prop, n);
    { dim3 g(HH / 128, cdiv(n, 128)); sgemm2<<<g, 256>>>(prop, W1, b1, h, n, HH, FF, 1); }
    // ----- layer 2 -----
    k_aggr<HH><<<aggr_blocks, T>>>(eoff, esrc, inv, h, prop, n);
    { dim3 g(HH / 128, cdiv(n, 128)); sgemm2<<<g, 256>>>(prop, W2, b2, h, n, HH, HH, 1); }
    // ----- layer 3 -----
    k_aggr<HH><<<aggr_blocks, T>>>(eoff, esrc, inv, h, prop, n);
    { dim3 g(CC / 128, cdiv(n, 128)); sgemm2<<<g, 256>>>(prop, W3, b3, h3, n, CC, HH, 1); }

    // ----- softmax + cluster assignment (writes S) -----
    k_softmax_argmax<<<cdiv(n * 32, T), T>>>(h3, out + off_s, cluster, n);

    // ----- score layer on intra-cluster subgraph -----
    k_reset_cluster<<<cdiv(CC, T), T>>>(segmax, segidx, intra, CC);
    k_intra<<<cdiv(n, T), T>>>(eoff, esrc, cluster, n, cnt, intra);
    k_inv<<<cdiv(n, T), T>>>(cnt, inv, n);
    k_z<<<cdiv(n * 32, T), T>>>(x, Ws, z, n);
    k_scoreagg<<<cdiv(n, T), T>>>(eoff, esrc, cluster, inv, z, bs, score, n);

    // ----- per-cluster top-1 selection -----
    k_segmax<<<cdiv(n, T), T>>>(score, cluster, segmax, n);
    k_segidx<<<cdiv(n, T), T>>>(score, cluster, segmax, segidx, n);

    // ----- outputs -----
    k_zero_f32<<<cdiv(CC * CC, T), T>>>(out + off_adj, CC * CC);
    k_adj<<<cdiv(E, T), T>>>(src, dst, cluster, intra, out + off_adj, E);
    k_finalize<<<CC, 128>>>(x, batch, segmax, segidx, intra, out, out + off_batch, n);
}